// round 13
// baseline (speedup 1.0000x reference)
#include <cuda_runtime.h>
#include <cuda_fp16.h>
#include <stdint.h>

#define DIM    5120
#define SQ     16384
#define KVLEN  257
#define KVP    288
#define NHEADS 40
#define HDIM   128
#define INV_DIM (1.0f / 5120.0f)
#define RMS_EPS 1e-6f

// ---------------- scratch (device globals; no allocs allowed) ----------------
__device__ __half g_Hh  [(size_t)SQ * DIM];
__device__ __half g_Eh  [(size_t)KVLEN * DIM];
__device__ __half g_Wqh [(size_t)DIM * DIM];
__device__ __half g_Wkh [(size_t)DIM * DIM];
__device__ __half g_Wvh [(size_t)DIM * DIM];
__device__ __half g_Qh  [(size_t)SQ * DIM];    // raw q (pre-norm), fp16
__device__ __half g_Kh  [(size_t)KVP * DIM];   // raw k; rows >= 257 stay zero
__device__ __half g_Vh  [(size_t)KVP * DIM];   // v; rows >= 257 stay zero
__device__ float  g_ssq_q[SQ];
__device__ float  g_ssq_k[KVLEN];

// ---------------- helpers ----------------
__device__ __forceinline__ uint32_t smem_u32(const void* p) {
    return (uint32_t)__cvta_generic_to_shared(p);
}

__device__ __forceinline__ uint32_t h2_as_u32(__half2 h) {
    return *reinterpret_cast<uint32_t*>(&h);
}

__device__ __forceinline__ void ldmx4(uint32_t& r0, uint32_t& r1, uint32_t& r2, uint32_t& r3,
                                      const __half* p) {
    asm volatile("ldmatrix.sync.aligned.m8n8.x4.shared.b16 {%0,%1,%2,%3}, [%4];"
                 : "=r"(r0), "=r"(r1), "=r"(r2), "=r"(r3)
                 : "r"(smem_u32(p)));
}

__device__ __forceinline__ void ldmx4t(uint32_t& r0, uint32_t& r1, uint32_t& r2, uint32_t& r3,
                                       const __half* p) {
    asm volatile("ldmatrix.sync.aligned.m8n8.x4.trans.shared.b16 {%0,%1,%2,%3}, [%4];"
                 : "=r"(r0), "=r"(r1), "=r"(r2), "=r"(r3)
                 : "r"(smem_u32(p)));
}

__device__ __forceinline__ void mma16816(float* c, const uint32_t* a, const uint32_t* b) {
    asm volatile(
        "mma.sync.aligned.m16n8k16.row.col.f32.f16.f16.f32 "
        "{%0,%1,%2,%3},{%4,%5,%6,%7},{%8,%9},{%0,%1,%2,%3};"
        : "+f"(c[0]), "+f"(c[1]), "+f"(c[2]), "+f"(c[3])
        : "r"(a[0]), "r"(a[1]), "r"(a[2]), "r"(a[3]), "r"(b[0]), "r"(b[1]));
}

__device__ __forceinline__ void cp16(uint32_t dst, const void* src, bool pred) {
    asm volatile("cp.async.cg.shared.global [%0], [%1], 16, %2;"
                 :: "r"(dst), "l"(src), "r"(pred ? 16 : 0) : "memory");
}
#define CP_COMMIT() asm volatile("cp.async.commit_group;" ::: "memory")
#define CP_WAIT1()  asm volatile("cp.async.wait_group 1;" ::: "memory")

// ---------------- prep kernels (split so Q-GEMM lands at my launch #3) ----------------
__global__ void k_prep_hwq(const float* __restrict__ H, const float* __restrict__ Wq) {
    const size_t PH = (size_t)SQ * DIM / 2;
    const size_t PW = (size_t)DIM * DIM / 2;
    size_t i0 = (size_t)blockIdx.x * blockDim.x + threadIdx.x;
    size_t st = (size_t)gridDim.x * blockDim.x;
    if (i0 < SQ) g_ssq_q[i0] = 0.f;
    if (i0 < KVLEN) g_ssq_k[i0] = 0.f;
    for (size_t i = i0; i < PH + PW; i += st) {
        if (i < PH) {
            float2 v = ((const float2*)H)[i];
            ((__half2*)g_Hh)[i] = __floats2half2_rn(v.x, v.y);
        } else {
            float2 v = ((const float2*)Wq)[i - PH];
            ((__half2*)g_Wqh)[i - PH] = __floats2half2_rn(v.x, v.y);
        }
    }
}

__global__ void k_prep_rest(const float* __restrict__ Wk, const float* __restrict__ Wv,
                            const float* __restrict__ E) {
    const size_t PW = (size_t)DIM * DIM / 2;
    const size_t PE = (size_t)KVLEN * DIM / 2;
    size_t i0 = (size_t)blockIdx.x * blockDim.x + threadIdx.x;
    size_t st = (size_t)gridDim.x * blockDim.x;
    for (size_t i = i0; i < 2 * PW + PE; i += st) {
        if (i < PW) {
            float2 v = ((const float2*)Wk)[i];
            ((__half2*)g_Wkh)[i] = __floats2half2_rn(v.x, v.y);
        } else if (i < 2 * PW) {
            float2 v = ((const float2*)Wv)[i - PW];
            ((__half2*)g_Wvh)[i - PW] = __floats2half2_rn(v.x, v.y);
        } else {
            float2 v = ((const float2*)E)[i - 2 * PW];
            ((__half2*)g_Eh)[i - 2 * PW] = __floats2half2_rn(v.x, v.y);
        }
    }
}

// ---------------- projection GEMM core: 256 thr, 8 warps (4m x 2n), 32x64 warp tiles ----
// CTA 128x128, BK=32, 3-stage cp.async; 2 CTAs/SM (16 warps) for latency hiding.
#define P_STAGE  10240                   // halves per stage: A 128*40 + B 128*40
#define P_SMEM   (3 * P_STAGE * 2)       // 61440 bytes
#define P_NIT    (DIM / 32)              // 160

__device__ __forceinline__
void proj_body(const __half* __restrict__ A, const __half* __restrict__ W,
               const float* __restrict__ bias, int M,
               __half* __restrict__ out, float* __restrict__ ssq,
               int m0, int n0, __half* smh) {
    const int tid = threadIdx.x, lane = tid & 31, wid = tid >> 5;
    const int wm = wid & 3, wn = wid >> 2;   // 4m x 2n

    auto load_stage = [&](int s) {
        const int kk = s * 32;
        __half* st = smh + (s % 3) * P_STAGE;
#pragma unroll
        for (int j = 0; j < 2; j++) {        // A: 512 x 16B chunks, 2/thread
            int ch = tid + j * 256;
            int r = ch >> 2, c16 = ch & 3;
            int row = m0 + r;
            bool ok = row < M;
            cp16(smem_u32(&st[r * 40 + c16 * 8]),
                 A + (size_t)(ok ? row : 0) * DIM + kk + c16 * 8, ok);
        }
        __half* bt = st + 5120;
#pragma unroll
        for (int j = 0; j < 2; j++) {        // B: 512 x 16B chunks, 2/thread
            int ch = tid + j * 256;
            int r = ch >> 2, c16 = ch & 3;
            cp16(smem_u32(&bt[r * 40 + c16 * 8]),
                 W + (size_t)(n0 + r) * DIM + kk + c16 * 8, true);
        }
        CP_COMMIT();
    };

    float acc[2][8][4];
#pragma unroll
    for (int i = 0; i < 2; i++)
#pragma unroll
        for (int j = 0; j < 8; j++)
#pragma unroll
            for (int k = 0; k < 4; k++) acc[i][j][k] = 0.f;

    load_stage(0);
    load_stage(1);

    for (int i = 0; i < P_NIT; i++) {
        CP_WAIT1();          // stage i resident
        __syncthreads();     // all warps done with buffer (i+2)%3
        if (i + 2 < P_NIT) load_stage(i + 2);
        else CP_COMMIT();    // empty group keeps wait count uniform

        const __half* a_s = smh + (i % 3) * P_STAGE;
        const __half* b_s = a_s + 5120;

#pragma unroll
        for (int ks = 0; ks < 32; ks += 16) {
            uint32_t af[2][4];
#pragma unroll
            for (int mf = 0; mf < 2; mf++) {
                int mr = wm * 32 + mf * 16 + (lane & 7) + ((lane >> 3) & 1) * 8;
                int mc = ks + (lane >> 4) * 8;
                ldmx4(af[mf][0], af[mf][1], af[mf][2], af[mf][3], &a_s[mr * 40 + mc]);
            }
#pragma unroll
            for (int np = 0; np < 4; np++) {   // B fragments consumed in place
                uint32_t b0[2], b1[2];
                int nr = wn * 64 + np * 16 + (lane & 7) + ((lane >> 4) ? 8 : 0);
                int nc = ks + (((lane >> 3) & 1) ? 8 : 0);
                ldmx4(b0[0], b0[1], b1[0], b1[1], &b_s[nr * 40 + nc]);
#pragma unroll
                for (int mf = 0; mf < 2; mf++) {
                    mma16816(acc[mf][2 * np + 0], af[mf], b0);
                    mma16816(acc[mf][2 * np + 1], af[mf], b1);
                }
            }
        }
    }

    // epilogue: fp16 store (+ optional row sum-of-squares)
#pragma unroll
    for (int mf = 0; mf < 2; mf++) {
#pragma unroll
        for (int rh = 0; rh < 2; rh++) {
            int gr = m0 + wm * 32 + mf * 16 + (lane >> 2) + rh * 8;
            if (gr >= M) continue;
            float s = 0.f;
#pragma unroll
            for (int nf = 0; nf < 8; nf++) {
                int gc = n0 + wn * 64 + nf * 8 + 2 * (lane & 3);
                float v0 = acc[mf][nf][rh * 2 + 0] + bias[gc];
                float v1 = acc[mf][nf][rh * 2 + 1] + bias[gc + 1];
                s += v0 * v0 + v1 * v1;
                *(__half2*)&out[(size_t)gr * DIM + gc] = __floats2half2_rn(v0, v1);
            }
            if (ssq) atomicAdd(&ssq[gr], s);
        }
    }
}

__global__ __launch_bounds__(256, 2)
void k_proj_q(const __half* __restrict__ A, const __half* __restrict__ W,
              const float* __restrict__ bias, __half* __restrict__ out,
              float* __restrict__ ssq) {
    extern __shared__ __align__(16) __half smh[];
    proj_body(A, W, bias, SQ, out, ssq, blockIdx.y * 128, blockIdx.x * 128, smh);
}

__global__ __launch_bounds__(256, 2)
void k_proj_kv(const __half* __restrict__ E,
               const __half* __restrict__ Wk, const __half* __restrict__ Wv,
               const float* __restrict__ bk, const float* __restrict__ bv,
               __half* __restrict__ Kh, __half* __restrict__ Vh,
               float* __restrict__ ssq_k) {
    extern __shared__ __align__(16) __half smh[];
    if (blockIdx.z == 0)
        proj_body(E, Wk, bk, KVLEN, Kh, ssq_k, blockIdx.y * 128, blockIdx.x * 128, smh);
    else
        proj_body(E, Wv, bv, KVLEN, Vh, (float*)0, blockIdx.y * 128, blockIdx.x * 128, smh);
}

// ---------------- register-streaming flash attention (round-12 proven) ----------------
#define AT_STRIDE 136
#define AT_QS_HALFS (64 * AT_STRIDE)
#define AT_KV_CHUNK (16 * AT_STRIDE)
#define AT_STAGE    (2 * AT_KV_CHUNK)
#define AT_SMEM     ((AT_QS_HALFS + 3 * AT_STAGE) * 2 + KVP * 4)
#define AT_NCH      17

__global__ __launch_bounds__(128, 3)
void k_attn(const float* __restrict__ gq, const float* __restrict__ gk,
            float* __restrict__ out) {
    extern __shared__ __align__(16) char smem[];
    __half* Qs = (__half*)smem;
    __half* KV = (__half*)(smem + AT_QS_HALFS * 2);
    float* kscale = (float*)(smem + (AT_QS_HALFS + 3 * AT_STAGE) * 2);

    const int tid = threadIdx.x, lane = tid & 31, wid = tid >> 5;
    const int m0 = blockIdx.x * 64;
    const size_t hc = (size_t)blockIdx.y * HDIM;
    const float SCALE = 0.088388347648318447f;

    for (int c = tid; c < KVP; c += 128)
        kscale[c] = (c < KVLEN) ? rsqrtf(g_ssq_k[c] * INV_DIM + RMS_EPS) : 0.f;

    auto load_kv = [&](int s) {
        __half* base = KV + (s % 3) * AT_STAGE;
        const __half* Ksrc = g_Kh + (size_t)(s * 16) * DIM + hc;
        const __half* Vsrc = g_Vh + (size_t)(s * 16) * DIM + hc;
#pragma unroll
        for (int j = 0; j < 2; j++) {
            int ch = tid + j * 128;
            int r = ch >> 4, c8 = (ch & 15) * 8;
            cp16(smem_u32(&base[r * AT_STRIDE + c8]), Ksrc + (size_t)r * DIM + c8, true);
        }
#pragma unroll
        for (int j = 0; j < 2; j++) {
            int ch = tid + j * 128;
            int r = ch >> 4, c8 = (ch & 15) * 8;
            cp16(smem_u32(&base[AT_KV_CHUNK + r * AT_STRIDE + c8]),
                 Vsrc + (size_t)r * DIM + c8, true);
        }
        CP_COMMIT();
    };
    load_kv(0);
    load_kv(1);

#pragma unroll
    for (int i = 0; i < 8; i++) {
        int idx = tid + 128 * i;
        int r = idx >> 4, c = (idx & 15) * 8;
        float sc = rsqrtf(g_ssq_q[m0 + r] * INV_DIM + RMS_EPS);
        uint4 v = *(const uint4*)&g_Qh[(size_t)(m0 + r) * DIM + hc + c];
        __half2* hv = (__half2*)&v;
        const float2* gqp = (const float2*)(gq + hc + c);
        const float2* gkp = (const float2*)(gk + hc + c);
#pragma unroll
        for (int j = 0; j < 4; j++) {
            float2 f = __half22float2(hv[j]);
            float2 a = gqp[j], b = gkp[j];
            hv[j] = __floats2half2_rn(f.x * sc * a.x * b.x, f.y * sc * a.y * b.y);
        }
        *(uint4*)&Qs[r * AT_STRIDE + c] = v;
    }
    __syncthreads();

    uint32_t qf[8][4];
#pragma unroll
    for (int kk = 0; kk < 8; kk++) {
        int mr = wid * 16 + (lane & 7) + ((lane >> 3) & 1) * 8;
        int mc = kk * 16 + (lane >> 4) * 8;
        ldmx4(qf[kk][0], qf[kk][1], qf[kk][2], qf[kk][3], &Qs[mr * AT_STRIDE + mc]);
    }

    float oacc[16][4];
#pragma unroll
    for (int i = 0; i < 16; i++)
#pragma unroll
        for (int j = 0; j < 4; j++) oacc[i][j] = 0.f;
    float s0 = 0.f, s1 = 0.f;

    for (int chk = 0; chk < AT_NCH; chk++) {
        CP_WAIT1();
        __syncthreads();
        if (chk + 2 < AT_NCH) load_kv(chk + 2);
        else CP_COMMIT();

        const __half* Kc = KV + (chk % 3) * AT_STAGE;
        const __half* Vc = Kc + AT_KV_CHUNK;

        float sacc[2][4];
#pragma unroll
        for (int t = 0; t < 2; t++)
#pragma unroll
            for (int j = 0; j < 4; j++) sacc[t][j] = 0.f;
#pragma unroll
        for (int kk = 0; kk < 8; kk++) {
            uint32_t b0[2], b1[2];
            int nr = (lane & 7) + ((lane >> 4) ? 8 : 0);
            int nc = kk * 16 + (((lane >> 3) & 1) ? 8 : 0);
            ldmx4(b0[0], b0[1], b1[0], b1[1], &Kc[nr * AT_STRIDE + nc]);
            mma16816(sacc[0], qf[kk], b0);
            mma16816(sacc[1], qf[kk], b1);
        }

        uint32_t pf[4];
#pragma unroll
        for (int nt = 0; nt < 2; nt++) {
            int c0 = chk * 16 + nt * 8 + 2 * (lane & 3);
            float k0 = kscale[c0], k1 = kscale[c0 + 1];
            float e0 = (c0 < KVLEN) ? __expf(sacc[nt][0] * SCALE * k0) : 0.f;
            float e1 = (c0 + 1 < KVLEN) ? __expf(sacc[nt][1] * SCALE * k1) : 0.f;
            float e2 = (c0 < KVLEN) ? __expf(sacc[nt][2] * SCALE * k0) : 0.f;
            float e3 = (c0 + 1 < KVLEN) ? __expf(sacc[nt][3] * SCALE * k1) : 0.f;
            s0 += e0 + e1;
            s1 += e2 + e3;
            pf[nt * 2 + 0] = h2_as_u32(__floats2half2_rn(e0, e1));
            pf[nt * 2 + 1] = h2_as_u32(__floats2half2_rn(e2, e3));
        }

#pragma unroll
        for (int np = 0; np < 8; np++) {
            uint32_t v0[2], v1[2];
            int vr = (lane & 7) + ((lane >> 3) & 1) * 8;
            int vc = np * 16 + (lane >> 4) * 8;
            ldmx4t(v0[0], v0[1], v1[0], v1[1], &Vc[vr * AT_STRIDE + vc]);
            mma16816(oacc[2 * np + 0], pf, v0);
            mma16816(oacc[2 * np + 1], pf, v1);
        }
    }

    s0 += __shfl_xor_sync(0xffffffffu, s0, 1);
    s0 += __shfl_xor_sync(0xffffffffu, s0, 2);
    s1 += __shfl_xor_sync(0xffffffffu, s1, 1);
    s1 += __shfl_xor_sync(0xffffffffu, s1, 2);
    float inv0 = 1.0f / s0, inv1 = 1.0f / s1;

    int r0 = m0 + wid * 16 + (lane >> 2);
    size_t o0 = (size_t)r0 * DIM + hc;
    size_t o1 = (size_t)(r0 + 8) * DIM + hc;
#pragma unroll
    for (int nt = 0; nt < 16; nt++) {
        int c = nt * 8 + 2 * (lane & 3);
        *(float2*)&out[o0 + c] = make_float2(oacc[nt][0] * inv0, oacc[nt][1] * inv0);
        *(float2*)&out[o1 + c] = make_float2(oacc[nt][2] * inv1, oacc[nt][3] * inv1);
    }
}

// ---------------- launcher ----------------
extern "C" void kernel_launch(void* const* d_in, const int* in_sizes, int n_in,
                              void* d_out, int out_size) {
    const float* hidden = (const float*)d_in[0];
    const float* enc = (const float*)d_in[1];
    const float* wq = (const float*)d_in[2];
    const float* bq = (const float*)d_in[3];
    const float* wk = (const float*)d_in[4];
    const float* bk = (const float*)d_in[5];
    const float* wv = (const float*)d_in[6];
    const float* bv = (const float*)d_in[7];
    const float* gq = (const float*)d_in[8];
    const float* gk = (const float*)d_in[9];
    float* out = (float*)d_out;

    void* p;
    cudaGetSymbolAddress(&p, g_Hh);    __half* Hh = (__half*)p;
    cudaGetSymbolAddress(&p, g_Eh);    __half* Eh = (__half*)p;
    cudaGetSymbolAddress(&p, g_Wqh);   __half* Wqh = (__half*)p;
    cudaGetSymbolAddress(&p, g_Wkh);   __half* Wkh = (__half*)p;
    cudaGetSymbolAddress(&p, g_Wvh);   __half* Wvh = (__half*)p;
    cudaGetSymbolAddress(&p, g_Qh);    __half* Qh = (__half*)p;
    cudaGetSymbolAddress(&p, g_Kh);    __half* Kh = (__half*)p;
    cudaGetSymbolAddress(&p, g_Vh);    __half* Vh = (__half*)p;
    cudaGetSymbolAddress(&p, g_ssq_q); float* ssq_q = (float*)p;
    cudaGetSymbolAddress(&p, g_ssq_k); float* ssq_k = (float*)p;

    // launch 0: H + Wq -> fp16, ssq zeroed
    k_prep_hwq<<<4096, 256>>>(hidden, wq);
    // launch 1: Wk, Wv, enc -> fp16
    k_prep_rest<<<2048, 256>>>(wk, wv, enc);
    // launch 2: K and V projections merged
    cudaFuncSetAttribute(k_proj_kv, cudaFuncAttributeMaxDynamicSharedMemorySize, P_SMEM);
    k_proj_kv<<<dim3(40, 3, 2), 256, P_SMEM>>>(Eh, Wkh, Wvh, bk, bv, Kh, Vh, ssq_k);
    // launch 3: Q projection GEMM, 8 warps / 2 CTAs per SM (ncu profiles this slot)
    cudaFuncSetAttribute(k_proj_q, cudaFuncAttributeMaxDynamicSharedMemorySize, P_SMEM);
    k_proj_q<<<dim3(40, 128), 256, P_SMEM>>>(Hh, Wqh, bq, Qh, ssq_q);
    // launch 4: streaming flash attention
    cudaFuncSetAttribute(k_attn, cudaFuncAttributeMaxDynamicSharedMemorySize, AT_SMEM);
    k_attn<<<dim3(SQ / 64, NHEADS), 128, AT_SMEM>>>(gq, gk, out);
}

// round 14
// speedup vs baseline: 1.0267x; 1.0267x over previous
#include <cuda_runtime.h>
#include <cuda_fp16.h>
#include <stdint.h>

#define DIM    5120
#define SQ     16384
#define KVLEN  257
#define KVP    288
#define NHEADS 40
#define HDIM   128
#define INV_DIM (1.0f / 5120.0f)
#define RMS_EPS 1e-6f

// ---------------- scratch (device globals; no allocs allowed) ----------------
__device__ __half g_Hh  [(size_t)SQ * DIM];
__device__ __half g_Eh  [(size_t)KVLEN * DIM];
__device__ __half g_Wqh [(size_t)DIM * DIM];
__device__ __half g_Wkh [(size_t)DIM * DIM];
__device__ __half g_Wvh [(size_t)DIM * DIM];
__device__ __half g_Qh  [(size_t)SQ * DIM];    // raw q (pre-norm), fp16
__device__ __half g_Kh  [(size_t)KVP * DIM];   // raw k; rows >= 257 stay zero
__device__ __half g_Vh  [(size_t)KVP * DIM];   // v; rows >= 257 stay zero
__device__ float  g_ssq_q[SQ];
__device__ float  g_ssq_k[KVLEN];

// ---------------- helpers ----------------
__device__ __forceinline__ uint32_t smem_u32(const void* p) {
    return (uint32_t)__cvta_generic_to_shared(p);
}

__device__ __forceinline__ uint32_t h2_as_u32(__half2 h) {
    return *reinterpret_cast<uint32_t*>(&h);
}

__device__ __forceinline__ void ldmx4(uint32_t& r0, uint32_t& r1, uint32_t& r2, uint32_t& r3,
                                      const __half* p) {
    asm volatile("ldmatrix.sync.aligned.m8n8.x4.shared.b16 {%0,%1,%2,%3}, [%4];"
                 : "=r"(r0), "=r"(r1), "=r"(r2), "=r"(r3)
                 : "r"(smem_u32(p)));
}

__device__ __forceinline__ void ldmx4t(uint32_t& r0, uint32_t& r1, uint32_t& r2, uint32_t& r3,
                                       const __half* p) {
    asm volatile("ldmatrix.sync.aligned.m8n8.x4.trans.shared.b16 {%0,%1,%2,%3}, [%4];"
                 : "=r"(r0), "=r"(r1), "=r"(r2), "=r"(r3)
                 : "r"(smem_u32(p)));
}

__device__ __forceinline__ void mma16816(float* c, const uint32_t* a, const uint32_t* b) {
    asm volatile(
        "mma.sync.aligned.m16n8k16.row.col.f32.f16.f16.f32 "
        "{%0,%1,%2,%3},{%4,%5,%6,%7},{%8,%9},{%0,%1,%2,%3};"
        : "+f"(c[0]), "+f"(c[1]), "+f"(c[2]), "+f"(c[3])
        : "r"(a[0]), "r"(a[1]), "r"(a[2]), "r"(a[3]), "r"(b[0]), "r"(b[1]));
}

__device__ __forceinline__ void cp16(uint32_t dst, const void* src, bool pred) {
    asm volatile("cp.async.cg.shared.global [%0], [%1], 16, %2;"
                 :: "r"(dst), "l"(src), "r"(pred ? 16 : 0) : "memory");
}
#define CP_COMMIT() asm volatile("cp.async.commit_group;" ::: "memory")
#define CP_WAIT1()  asm volatile("cp.async.wait_group 1;" ::: "memory")

// ---------------- merged prep: all fp32->fp16 conversions + ssq zeroing ----------------
__global__ void k_prep(const float* __restrict__ H, const float* __restrict__ Wq,
                       const float* __restrict__ Wk, const float* __restrict__ Wv,
                       const float* __restrict__ E) {
    const size_t PH = (size_t)SQ * DIM / 2;
    const size_t PW = (size_t)DIM * DIM / 2;
    const size_t PE = (size_t)KVLEN * DIM / 2;
    size_t i0 = (size_t)blockIdx.x * blockDim.x + threadIdx.x;
    size_t st = (size_t)gridDim.x * blockDim.x;
    if (i0 < SQ) g_ssq_q[i0] = 0.f;
    if (i0 < KVLEN) g_ssq_k[i0] = 0.f;
    const size_t total = PH + 3 * PW + PE;
    for (size_t i = i0; i < total; i += st) {
        if (i < PH) {
            float2 v = ((const float2*)H)[i];
            ((__half2*)g_Hh)[i] = __floats2half2_rn(v.x, v.y);
        } else if (i < PH + PW) {
            size_t j = i - PH;
            float2 v = ((const float2*)Wq)[j];
            ((__half2*)g_Wqh)[j] = __floats2half2_rn(v.x, v.y);
        } else if (i < PH + 2 * PW) {
            size_t j = i - PH - PW;
            float2 v = ((const float2*)Wk)[j];
            ((__half2*)g_Wkh)[j] = __floats2half2_rn(v.x, v.y);
        } else if (i < PH + 3 * PW) {
            size_t j = i - PH - 2 * PW;
            float2 v = ((const float2*)Wv)[j];
            ((__half2*)g_Wvh)[j] = __floats2half2_rn(v.x, v.y);
        } else {
            size_t j = i - PH - 3 * PW;
            float2 v = ((const float2*)E)[j];
            ((__half2*)g_Eh)[j] = __floats2half2_rn(v.x, v.y);
        }
    }
}

// ---------------- projection GEMM core (r12 proven: 4 warps, 64x64, BK=32, 3-stage) ----
#define P_STAGE  10240
#define P_SMEM   (3 * P_STAGE * 2)
#define P_NIT    (DIM / 32)

__device__ __forceinline__
void proj_body(const __half* __restrict__ A, const __half* __restrict__ W,
               const float* __restrict__ bias, int M,
               __half* __restrict__ out, float* __restrict__ ssq,
               int m0, int n0, __half* smh) {
    const int tid = threadIdx.x, lane = tid & 31, wid = tid >> 5;
    const int wm = wid & 1, wn = wid >> 1;

    auto load_stage = [&](int s) {
        const int kk = s * 32;
        __half* st = smh + (s % 3) * P_STAGE;
#pragma unroll
        for (int j = 0; j < 4; j++) {
            int ch = tid + j * 128;
            int r = ch >> 2, c16 = ch & 3;
            int row = m0 + r;
            bool ok = row < M;
            cp16(smem_u32(&st[r * 40 + c16 * 8]),
                 A + (size_t)(ok ? row : 0) * DIM + kk + c16 * 8, ok);
        }
        __half* bt = st + 5120;
#pragma unroll
        for (int j = 0; j < 4; j++) {
            int ch = tid + j * 128;
            int r = ch >> 2, c16 = ch & 3;
            cp16(smem_u32(&bt[r * 40 + c16 * 8]),
                 W + (size_t)(n0 + r) * DIM + kk + c16 * 8, true);
        }
        CP_COMMIT();
    };

    float acc[4][8][4];
#pragma unroll
    for (int i = 0; i < 4; i++)
#pragma unroll
        for (int j = 0; j < 8; j++)
#pragma unroll
            for (int k = 0; k < 4; k++) acc[i][j][k] = 0.f;

    load_stage(0);
    load_stage(1);

    for (int i = 0; i < P_NIT; i++) {
        CP_WAIT1();
        __syncthreads();
        if (i + 2 < P_NIT) load_stage(i + 2);
        else CP_COMMIT();

        const __half* a_s = smh + (i % 3) * P_STAGE;
        const __half* b_s = a_s + 5120;

#pragma unroll
        for (int ks = 0; ks < 32; ks += 16) {
            uint32_t af[4][4];
#pragma unroll
            for (int mf = 0; mf < 4; mf++) {
                int mr = wm * 64 + mf * 16 + (lane & 7) + ((lane >> 3) & 1) * 8;
                int mc = ks + (lane >> 4) * 8;
                ldmx4(af[mf][0], af[mf][1], af[mf][2], af[mf][3], &a_s[mr * 40 + mc]);
            }
#pragma unroll
            for (int np = 0; np < 4; np++) {
                uint32_t b0[2], b1[2];
                int nr = wn * 64 + np * 16 + (lane & 7) + ((lane >> 4) ? 8 : 0);
                int nc = ks + (((lane >> 3) & 1) ? 8 : 0);
                ldmx4(b0[0], b0[1], b1[0], b1[1], &b_s[nr * 40 + nc]);
#pragma unroll
                for (int mf = 0; mf < 4; mf++) {
                    mma16816(acc[mf][2 * np + 0], af[mf], b0);
                    mma16816(acc[mf][2 * np + 1], af[mf], b1);
                }
            }
        }
    }

#pragma unroll
    for (int mf = 0; mf < 4; mf++) {
#pragma unroll
        for (int rh = 0; rh < 2; rh++) {
            int gr = m0 + wm * 64 + mf * 16 + (lane >> 2) + rh * 8;
            if (gr >= M) continue;
            float s = 0.f;
#pragma unroll
            for (int nf = 0; nf < 8; nf++) {
                int gc = n0 + wn * 64 + nf * 8 + 2 * (lane & 3);
                float v0 = acc[mf][nf][rh * 2 + 0] + bias[gc];
                float v1 = acc[mf][nf][rh * 2 + 1] + bias[gc + 1];
                s += v0 * v0 + v1 * v1;
                *(__half2*)&out[(size_t)gr * DIM + gc] = __floats2half2_rn(v0, v1);
            }
            if (ssq) atomicAdd(&ssq[gr], s);
        }
    }
}

__global__ __launch_bounds__(128, 3)
void k_proj_q(const __half* __restrict__ A, const __half* __restrict__ W,
              const float* __restrict__ bias, __half* __restrict__ out,
              float* __restrict__ ssq) {
    extern __shared__ __align__(16) __half smh[];
    proj_body(A, W, bias, SQ, out, ssq, blockIdx.y * 128, blockIdx.x * 128, smh);
}

__global__ __launch_bounds__(128, 3)
void k_proj_kv(const __half* __restrict__ E,
               const __half* __restrict__ Wk, const __half* __restrict__ Wv,
               const float* __restrict__ bk, const float* __restrict__ bv,
               __half* __restrict__ Kh, __half* __restrict__ Vh,
               float* __restrict__ ssq_k) {
    extern __shared__ __align__(16) __half smh[];
    if (blockIdx.z == 0)
        proj_body(E, Wk, bk, KVLEN, Kh, ssq_k, blockIdx.y * 128, blockIdx.x * 128, smh);
    else
        proj_body(E, Wv, bv, KVLEN, Vh, (float*)0, blockIdx.y * 128, blockIdx.x * 128, smh);
}

// ---------------- register-streaming flash attention: 32-row KV chunks ----------------
// 128 threads = 4 warps; CTA = 64 q-rows x 1 head; each warp owns 16 q-rows.
#define AT_STRIDE 136
#define AT_QS_HALFS (64 * AT_STRIDE)           // 8704
#define AT_KV_CHUNK (32 * AT_STRIDE)           // 4352 halfs per K or V chunk
#define AT_STAGE    (2 * AT_KV_CHUNK)          // 8704 halfs
#define AT_SMEM     ((AT_QS_HALFS + 3 * AT_STAGE) * 2 + KVP * 4)  // ~70.8 KB
#define AT_NCH      9                           // 9*32 = 288 >= 257

__global__ __launch_bounds__(128, 3)
void k_attn(const float* __restrict__ gq, const float* __restrict__ gk,
            float* __restrict__ out) {
    extern __shared__ __align__(16) char smem[];
    __half* Qs = (__half*)smem;
    __half* KV = (__half*)(smem + AT_QS_HALFS * 2);
    float* kscale = (float*)(smem + (AT_QS_HALFS + 3 * AT_STAGE) * 2);

    const int tid = threadIdx.x, lane = tid & 31, wid = tid >> 5;
    const int m0 = blockIdx.x * 64;
    const size_t hc = (size_t)blockIdx.y * HDIM;
    const float SCALE = 0.088388347648318447f;  // 1/sqrt(128)

    // per-column K scale with softmax scale folded in (cols >= KVLEN masked later)
    for (int c = tid; c < KVP; c += 128)
        kscale[c] = (c < KVLEN) ? SCALE * rsqrtf(g_ssq_k[c] * INV_DIM + RMS_EPS) : 0.f;

    // KV chunk loader (3-stage cp.async ring; 32 rows of K + 32 rows of V)
    auto load_kv = [&](int s) {
        __half* base = KV + (s % 3) * AT_STAGE;
        const __half* Ksrc = g_Kh + (size_t)(s * 32) * DIM + hc;
        const __half* Vsrc = g_Vh + (size_t)(s * 32) * DIM + hc;
#pragma unroll
        for (int j = 0; j < 4; j++) {
            int ch = tid + j * 128;
            int r = ch >> 4, c8 = (ch & 15) * 8;
            cp16(smem_u32(&base[r * AT_STRIDE + c8]), Ksrc + (size_t)r * DIM + c8, true);
        }
#pragma unroll
        for (int j = 0; j < 4; j++) {
            int ch = tid + j * 128;
            int r = ch >> 4, c8 = (ch & 15) * 8;
            cp16(smem_u32(&base[AT_KV_CHUNK + r * AT_STRIDE + c8]),
                 Vsrc + (size_t)r * DIM + c8, true);
        }
        CP_COMMIT();
    };
    load_kv(0);
    load_kv(1);

    // Q tile 64x128: raw fp16 * qscale * gq * gk -> smem
#pragma unroll
    for (int i = 0; i < 8; i++) {
        int idx = tid + 128 * i;
        int r = idx >> 4, c = (idx & 15) * 8;
        float sc = rsqrtf(g_ssq_q[m0 + r] * INV_DIM + RMS_EPS);
        uint4 v = *(const uint4*)&g_Qh[(size_t)(m0 + r) * DIM + hc + c];
        __half2* hv = (__half2*)&v;
        const float2* gqp = (const float2*)(gq + hc + c);
        const float2* gkp = (const float2*)(gk + hc + c);
#pragma unroll
        for (int j = 0; j < 4; j++) {
            float2 f = __half22float2(hv[j]);
            float2 a = gqp[j], b = gkp[j];
            hv[j] = __floats2half2_rn(f.x * sc * a.x * b.x, f.y * sc * a.y * b.y);
        }
        *(uint4*)&Qs[r * AT_STRIDE + c] = v;
    }
    __syncthreads();

    // Q fragments: 16 rows (warp) x 128 k
    uint32_t qf[8][4];
#pragma unroll
    for (int kk = 0; kk < 8; kk++) {
        int mr = wid * 16 + (lane & 7) + ((lane >> 3) & 1) * 8;
        int mc = kk * 16 + (lane >> 4) * 8;
        ldmx4(qf[kk][0], qf[kk][1], qf[kk][2], qf[kk][3], &Qs[mr * AT_STRIDE + mc]);
    }

    float oacc[16][4];
#pragma unroll
    for (int i = 0; i < 16; i++)
#pragma unroll
        for (int j = 0; j < 4; j++) oacc[i][j] = 0.f;
    float s0 = 0.f, s1 = 0.f;

    for (int chk = 0; chk < AT_NCH; chk++) {
        CP_WAIT1();
        __syncthreads();
        if (chk + 2 < AT_NCH) load_kv(chk + 2);
        else CP_COMMIT();

        const __half* Kc = KV + (chk % 3) * AT_STAGE;
        const __half* Vc = Kc + AT_KV_CHUNK;

        // S = Q * K^T for this 32-col chunk (4 n-tiles of 8)
        float sacc[4][4];
#pragma unroll
        for (int t = 0; t < 4; t++)
#pragma unroll
            for (int j = 0; j < 4; j++) sacc[t][j] = 0.f;
#pragma unroll
        for (int kk = 0; kk < 8; kk++) {
#pragma unroll
            for (int half = 0; half < 2; half++) {
                uint32_t b0[2], b1[2];
                int nr = half * 16 + (lane & 7) + ((lane >> 4) ? 8 : 0);
                int nc = kk * 16 + (((lane >> 3) & 1) ? 8 : 0);
                ldmx4(b0[0], b0[1], b1[0], b1[1], &Kc[nr * AT_STRIDE + nc]);
                mma16816(sacc[half * 2 + 0], qf[kk], b0);
                mma16816(sacc[half * 2 + 1], qf[kk], b1);
            }
        }

        // exp(S * kscale[col]); pack two P A-fragments (k = 32)
        uint32_t pf[2][4];
        if (chk < 8) {  // all 32 cols valid: no masking
#pragma unroll
            for (int nt = 0; nt < 4; nt++) {
                int c0 = chk * 32 + nt * 8 + 2 * (lane & 3);
                float k0 = kscale[c0], k1 = kscale[c0 + 1];
                float e0 = __expf(sacc[nt][0] * k0);
                float e1 = __expf(sacc[nt][1] * k1);
                float e2 = __expf(sacc[nt][2] * k0);
                float e3 = __expf(sacc[nt][3] * k1);
                s0 += e0 + e1;
                s1 += e2 + e3;
                pf[nt >> 1][(nt & 1) * 2 + 0] = h2_as_u32(__floats2half2_rn(e0, e1));
                pf[nt >> 1][(nt & 1) * 2 + 1] = h2_as_u32(__floats2half2_rn(e2, e3));
            }
        } else {        // last chunk: cols 256..287, mask >= KVLEN
#pragma unroll
            for (int nt = 0; nt < 4; nt++) {
                int c0 = chk * 32 + nt * 8 + 2 * (lane & 3);
                float k0 = kscale[c0], k1 = kscale[c0 + 1];
                float e0 = (c0 < KVLEN) ? __expf(sacc[nt][0] * k0) : 0.f;
                float e1 = (c0 + 1 < KVLEN) ? __expf(sacc[nt][1] * k1) : 0.f;
                float e2 = (c0 < KVLEN) ? __expf(sacc[nt][2] * k0) : 0.f;
                float e3 = (c0 + 1 < KVLEN) ? __expf(sacc[nt][3] * k1) : 0.f;
                s0 += e0 + e1;
                s1 += e2 + e3;
                pf[nt >> 1][(nt & 1) * 2 + 0] = h2_as_u32(__floats2half2_rn(e0, e1));
                pf[nt >> 1][(nt & 1) * 2 + 1] = h2_as_u32(__floats2half2_rn(e2, e3));
            }
        }

        // O += P * V  (k = 32: two 16-row halves)
#pragma unroll
        for (int np = 0; np < 8; np++) {
#pragma unroll
            for (int kh = 0; kh < 2; kh++) {
                uint32_t v0[2], v1[2];
                int vr = kh * 16 + (lane & 7) + ((lane >> 3) & 1) * 8;
                int vc = np * 16 + (lane >> 4) * 8;
                ldmx4t(v0[0], v0[1], v1[0], v1[1], &Vc[vr * AT_STRIDE + vc]);
                mma16816(oacc[2 * np + 0], pf[kh], v0);
                mma16816(oacc[2 * np + 1], pf[kh], v1);
            }
        }
    }

    // rowsum: reduce over the 4 lanes sharing each row
    s0 += __shfl_xor_sync(0xffffffffu, s0, 1);
    s0 += __shfl_xor_sync(0xffffffffu, s0, 2);
    s1 += __shfl_xor_sync(0xffffffffu, s1, 1);
    s1 += __shfl_xor_sync(0xffffffffu, s1, 2);
    float inv0 = 1.0f / s0, inv1 = 1.0f / s1;

    int r0 = m0 + wid * 16 + (lane >> 2);
    size_t o0 = (size_t)r0 * DIM + hc;
    size_t o1 = (size_t)(r0 + 8) * DIM + hc;
#pragma unroll
    for (int nt = 0; nt < 16; nt++) {
        int c = nt * 8 + 2 * (lane & 3);
        *(float2*)&out[o0 + c] = make_float2(oacc[nt][0] * inv0, oacc[nt][1] * inv0);
        *(float2*)&out[o1 + c] = make_float2(oacc[nt][2] * inv1, oacc[nt][3] * inv1);
    }
}

// ---------------- launcher ----------------
extern "C" void kernel_launch(void* const* d_in, const int* in_sizes, int n_in,
                              void* d_out, int out_size) {
    const float* hidden = (const float*)d_in[0];
    const float* enc = (const float*)d_in[1];
    const float* wq = (const float*)d_in[2];
    const float* bq = (const float*)d_in[3];
    const float* wk = (const float*)d_in[4];
    const float* bk = (const float*)d_in[5];
    const float* wv = (const float*)d_in[6];
    const float* bv = (const float*)d_in[7];
    const float* gq = (const float*)d_in[8];
    const float* gk = (const float*)d_in[9];
    float* out = (float*)d_out;

    void* p;
    cudaGetSymbolAddress(&p, g_Hh);    __half* Hh = (__half*)p;
    cudaGetSymbolAddress(&p, g_Eh);    __half* Eh = (__half*)p;
    cudaGetSymbolAddress(&p, g_Wqh);   __half* Wqh = (__half*)p;
    cudaGetSymbolAddress(&p, g_Wkh);   __half* Wkh = (__half*)p;
    cudaGetSymbolAddress(&p, g_Wvh);   __half* Wvh = (__half*)p;
    cudaGetSymbolAddress(&p, g_Qh);    __half* Qh = (__half*)p;
    cudaGetSymbolAddress(&p, g_Kh);    __half* Kh = (__half*)p;
    cudaGetSymbolAddress(&p, g_Vh);    __half* Vh = (__half*)p;
    cudaGetSymbolAddress(&p, g_ssq_q); float* ssq_q = (float*)p;
    cudaGetSymbolAddress(&p, g_ssq_k); float* ssq_k = (float*)p;

    // launch 0: all conversions + ssq zeroing
    k_prep<<<6144, 256>>>(hidden, wq, wk, wv, enc);
    // launch 1: K and V projections merged
    cudaFuncSetAttribute(k_proj_kv, cudaFuncAttributeMaxDynamicSharedMemorySize, P_SMEM);
    k_proj_kv<<<dim3(40, 3, 2), 128, P_SMEM>>>(Eh, Wkh, Wvh, bk, bv, Kh, Vh, ssq_k);
    // launch 2: Q projection GEMM (r12 proven config)
    cudaFuncSetAttribute(k_proj_q, cudaFuncAttributeMaxDynamicSharedMemorySize, P_SMEM);
    k_proj_q<<<dim3(40, 128), 128, P_SMEM>>>(Hh, Wqh, bq, Qh, ssq_q);
    // launch 3: streaming flash attention, 32-row chunks (ncu profiles this slot)
    cudaFuncSetAttribute(k_attn, cudaFuncAttributeMaxDynamicSharedMemorySize, AT_SMEM);
    k_attn<<<dim3(SQ / 64, NHEADS), 128, AT_SMEM>>>(gq, gk, out);
}

// round 15
// speedup vs baseline: 1.0403x; 1.0132x over previous
#include <cuda_runtime.h>
#include <cuda_fp16.h>
#include <stdint.h>

#define DIM    5120
#define SQ     16384
#define KVLEN  257
#define KVP    288
#define NHEADS 40
#define HDIM   128
#define INV_DIM (1.0f / 5120.0f)
#define RMS_EPS 1e-6f

// ---------------- scratch (device globals; no allocs allowed) ----------------
__device__ __half g_Hh  [(size_t)SQ * DIM];
__device__ __half g_Eh  [(size_t)KVLEN * DIM];
__device__ __half g_Wqh [(size_t)DIM * DIM];
__device__ __half g_Wkh [(size_t)DIM * DIM];
__device__ __half g_Wvh [(size_t)DIM * DIM];
__device__ __half g_Qh  [(size_t)SQ * DIM];    // raw q (pre-norm), fp16
__device__ __half g_Kh  [(size_t)KVP * DIM];   // raw k; rows >= 257 stay zero
__device__ __half g_Vh  [(size_t)KVP * DIM];   // v; rows >= 257 stay zero
__device__ float  g_ssq_q[SQ];
__device__ float  g_ssq_k[KVLEN];

// ---------------- helpers ----------------
__device__ __forceinline__ uint32_t smem_u32(const void* p) {
    return (uint32_t)__cvta_generic_to_shared(p);
}

__device__ __forceinline__ uint32_t h2_as_u32(__half2 h) {
    return *reinterpret_cast<uint32_t*>(&h);
}

__device__ __forceinline__ void ldmx4(uint32_t& r0, uint32_t& r1, uint32_t& r2, uint32_t& r3,
                                      const __half* p) {
    asm volatile("ldmatrix.sync.aligned.m8n8.x4.shared.b16 {%0,%1,%2,%3}, [%4];"
                 : "=r"(r0), "=r"(r1), "=r"(r2), "=r"(r3)
                 : "r"(smem_u32(p)));
}

__device__ __forceinline__ void ldmx4t(uint32_t& r0, uint32_t& r1, uint32_t& r2, uint32_t& r3,
                                       const __half* p) {
    asm volatile("ldmatrix.sync.aligned.m8n8.x4.trans.shared.b16 {%0,%1,%2,%3}, [%4];"
                 : "=r"(r0), "=r"(r1), "=r"(r2), "=r"(r3)
                 : "r"(smem_u32(p)));
}

__device__ __forceinline__ void mma16816(float* c, const uint32_t* a, const uint32_t* b) {
    asm volatile(
        "mma.sync.aligned.m16n8k16.row.col.f32.f16.f16.f32 "
        "{%0,%1,%2,%3},{%4,%5,%6,%7},{%8,%9},{%0,%1,%2,%3};"
        : "+f"(c[0]), "+f"(c[1]), "+f"(c[2]), "+f"(c[3])
        : "r"(a[0]), "r"(a[1]), "r"(a[2]), "r"(a[3]), "r"(b[0]), "r"(b[1]));
}

__device__ __forceinline__ void cp16(uint32_t dst, const void* src, bool pred) {
    asm volatile("cp.async.cg.shared.global [%0], [%1], 16, %2;"
                 :: "r"(dst), "l"(src), "r"(pred ? 16 : 0) : "memory");
}
#define CP_COMMIT() asm volatile("cp.async.commit_group;" ::: "memory")
#define CP_WAIT1()  asm volatile("cp.async.wait_group 1;" ::: "memory")

// ---------------- merged prep: all fp32->fp16 conversions + ssq zeroing ----------------
__global__ void k_prep(const float* __restrict__ H, const float* __restrict__ Wq,
                       const float* __restrict__ Wk, const float* __restrict__ Wv,
                       const float* __restrict__ E) {
    const size_t PH = (size_t)SQ * DIM / 2;
    const size_t PW = (size_t)DIM * DIM / 2;
    const size_t PE = (size_t)KVLEN * DIM / 2;
    size_t i0 = (size_t)blockIdx.x * blockDim.x + threadIdx.x;
    size_t st = (size_t)gridDim.x * blockDim.x;
    if (i0 < SQ) g_ssq_q[i0] = 0.f;
    if (i0 < KVLEN) g_ssq_k[i0] = 0.f;
    const size_t total = PH + 3 * PW + PE;
    for (size_t i = i0; i < total; i += st) {
        if (i < PH) {
            float2 v = ((const float2*)H)[i];
            ((__half2*)g_Hh)[i] = __floats2half2_rn(v.x, v.y);
        } else if (i < PH + PW) {
            size_t j = i - PH;
            float2 v = ((const float2*)Wq)[j];
            ((__half2*)g_Wqh)[j] = __floats2half2_rn(v.x, v.y);
        } else if (i < PH + 2 * PW) {
            size_t j = i - PH - PW;
            float2 v = ((const float2*)Wk)[j];
            ((__half2*)g_Wkh)[j] = __floats2half2_rn(v.x, v.y);
        } else if (i < PH + 3 * PW) {
            size_t j = i - PH - 2 * PW;
            float2 v = ((const float2*)Wv)[j];
            ((__half2*)g_Wvh)[j] = __floats2half2_rn(v.x, v.y);
        } else {
            size_t j = i - PH - 3 * PW;
            float2 v = ((const float2*)E)[j];
            ((__half2*)g_Eh)[j] = __floats2half2_rn(v.x, v.y);
        }
    }
}

// ---------------- projection GEMM core (r12 proven: 4 warps, 64x64, BK=32, 3-stage) ----
#define P_STAGE  10240
#define P_SMEM   (3 * P_STAGE * 2)
#define P_NIT    (DIM / 32)

__device__ __forceinline__
void proj_body(const __half* __restrict__ A, const __half* __restrict__ W,
               const float* __restrict__ bias, int M,
               __half* __restrict__ out, float* __restrict__ ssq,
               int m0, int n0, __half* smh) {
    const int tid = threadIdx.x, lane = tid & 31, wid = tid >> 5;
    const int wm = wid & 1, wn = wid >> 1;

    auto load_stage = [&](int s) {
        const int kk = s * 32;
        __half* st = smh + (s % 3) * P_STAGE;
#pragma unroll
        for (int j = 0; j < 4; j++) {
            int ch = tid + j * 128;
            int r = ch >> 2, c16 = ch & 3;
            int row = m0 + r;
            bool ok = row < M;
            cp16(smem_u32(&st[r * 40 + c16 * 8]),
                 A + (size_t)(ok ? row : 0) * DIM + kk + c16 * 8, ok);
        }
        __half* bt = st + 5120;
#pragma unroll
        for (int j = 0; j < 4; j++) {
            int ch = tid + j * 128;
            int r = ch >> 2, c16 = ch & 3;
            cp16(smem_u32(&bt[r * 40 + c16 * 8]),
                 W + (size_t)(n0 + r) * DIM + kk + c16 * 8, true);
        }
        CP_COMMIT();
    };

    float acc[4][8][4];
#pragma unroll
    for (int i = 0; i < 4; i++)
#pragma unroll
        for (int j = 0; j < 8; j++)
#pragma unroll
            for (int k = 0; k < 4; k++) acc[i][j][k] = 0.f;

    load_stage(0);
    load_stage(1);

    for (int i = 0; i < P_NIT; i++) {
        CP_WAIT1();
        __syncthreads();
        if (i + 2 < P_NIT) load_stage(i + 2);
        else CP_COMMIT();

        const __half* a_s = smh + (i % 3) * P_STAGE;
        const __half* b_s = a_s + 5120;

#pragma unroll
        for (int ks = 0; ks < 32; ks += 16) {
            uint32_t af[4][4];
#pragma unroll
            for (int mf = 0; mf < 4; mf++) {
                int mr = wm * 64 + mf * 16 + (lane & 7) + ((lane >> 3) & 1) * 8;
                int mc = ks + (lane >> 4) * 8;
                ldmx4(af[mf][0], af[mf][1], af[mf][2], af[mf][3], &a_s[mr * 40 + mc]);
            }
#pragma unroll
            for (int np = 0; np < 4; np++) {
                uint32_t b0[2], b1[2];
                int nr = wn * 64 + np * 16 + (lane & 7) + ((lane >> 4) ? 8 : 0);
                int nc = ks + (((lane >> 3) & 1) ? 8 : 0);
                ldmx4(b0[0], b0[1], b1[0], b1[1], &b_s[nr * 40 + nc]);
#pragma unroll
                for (int mf = 0; mf < 4; mf++) {
                    mma16816(acc[mf][2 * np + 0], af[mf], b0);
                    mma16816(acc[mf][2 * np + 1], af[mf], b1);
                }
            }
        }
    }

#pragma unroll
    for (int mf = 0; mf < 4; mf++) {
#pragma unroll
        for (int rh = 0; rh < 2; rh++) {
            int gr = m0 + wm * 64 + mf * 16 + (lane >> 2) + rh * 8;
            if (gr >= M) continue;
            float s = 0.f;
#pragma unroll
            for (int nf = 0; nf < 8; nf++) {
                int gc = n0 + wn * 64 + nf * 8 + 2 * (lane & 3);
                float v0 = acc[mf][nf][rh * 2 + 0] + bias[gc];
                float v1 = acc[mf][nf][rh * 2 + 1] + bias[gc + 1];
                s += v0 * v0 + v1 * v1;
                *(__half2*)&out[(size_t)gr * DIM + gc] = __floats2half2_rn(v0, v1);
            }
            if (ssq) atomicAdd(&ssq[gr], s);
        }
    }
}

// ---- ALL projections in one launch: bids 0..239 = K/V tiles, 240.. = Q tiles ----
// KV CTAs are placed first so they start in wave 1 and hide inside the Q-GEMM.
#define KV_CTAS 240   // 40 n-tiles x 3 m-tiles x 2 (K,V)

__global__ __launch_bounds__(128, 3)
void k_proj_all(const __half* __restrict__ Hh, const __half* __restrict__ Eh,
                const __half* __restrict__ Wq, const __half* __restrict__ Wk,
                const __half* __restrict__ Wv,
                const float* __restrict__ bq, const float* __restrict__ bk,
                const float* __restrict__ bv,
                __half* __restrict__ Qh, __half* __restrict__ Kh,
                __half* __restrict__ Vh,
                float* __restrict__ ssq_q, float* __restrict__ ssq_k) {
    extern __shared__ __align__(16) __half smh[];
    int bid = blockIdx.x;
    if (bid < KV_CTAS) {
        int n0 = (bid % 40) * 128;
        int rest = bid / 40;            // 0..5
        int m0 = (rest % 3) * 128;
        if (rest < 3)
            proj_body(Eh, Wk, bk, KVLEN, Kh, ssq_k, m0, n0, smh);
        else
            proj_body(Eh, Wv, bv, KVLEN, Vh, (float*)0, m0, n0, smh);
    } else {
        int q = bid - KV_CTAS;
        int n0 = (q % 40) * 128;
        int m0 = (q / 40) * 128;
        proj_body(Hh, Wq, bq, SQ, Qh, ssq_q, m0, n0, smh);
    }
}

// ---------------- register-streaming flash attention: 32-row KV chunks (r14 proven) ----
#define AT_STRIDE 136
#define AT_QS_HALFS (64 * AT_STRIDE)
#define AT_KV_CHUNK (32 * AT_STRIDE)
#define AT_STAGE    (2 * AT_KV_CHUNK)
#define AT_SMEM     ((AT_QS_HALFS + 3 * AT_STAGE) * 2 + KVP * 4)
#define AT_NCH      9

__global__ __launch_bounds__(128, 3)
void k_attn(const float* __restrict__ gq, const float* __restrict__ gk,
            float* __restrict__ out) {
    extern __shared__ __align__(16) char smem[];
    __half* Qs = (__half*)smem;
    __half* KV = (__half*)(smem + AT_QS_HALFS * 2);
    float* kscale = (float*)(smem + (AT_QS_HALFS + 3 * AT_STAGE) * 2);

    const int tid = threadIdx.x, lane = tid & 31, wid = tid >> 5;
    const int m0 = blockIdx.x * 64;
    const size_t hc = (size_t)blockIdx.y * HDIM;
    const float SCALE = 0.088388347648318447f;

    for (int c = tid; c < KVP; c += 128)
        kscale[c] = (c < KVLEN) ? SCALE * rsqrtf(g_ssq_k[c] * INV_DIM + RMS_EPS) : 0.f;

    auto load_kv = [&](int s) {
        __half* base = KV + (s % 3) * AT_STAGE;
        const __half* Ksrc = g_Kh + (size_t)(s * 32) * DIM + hc;
        const __half* Vsrc = g_Vh + (size_t)(s * 32) * DIM + hc;
#pragma unroll
        for (int j = 0; j < 4; j++) {
            int ch = tid + j * 128;
            int r = ch >> 4, c8 = (ch & 15) * 8;
            cp16(smem_u32(&base[r * AT_STRIDE + c8]), Ksrc + (size_t)r * DIM + c8, true);
        }
#pragma unroll
        for (int j = 0; j < 4; j++) {
            int ch = tid + j * 128;
            int r = ch >> 4, c8 = (ch & 15) * 8;
            cp16(smem_u32(&base[AT_KV_CHUNK + r * AT_STRIDE + c8]),
                 Vsrc + (size_t)r * DIM + c8, true);
        }
        CP_COMMIT();
    };
    load_kv(0);
    load_kv(1);

#pragma unroll
    for (int i = 0; i < 8; i++) {
        int idx = tid + 128 * i;
        int r = idx >> 4, c = (idx & 15) * 8;
        float sc = rsqrtf(g_ssq_q[m0 + r] * INV_DIM + RMS_EPS);
        uint4 v = *(const uint4*)&g_Qh[(size_t)(m0 + r) * DIM + hc + c];
        __half2* hv = (__half2*)&v;
        const float2* gqp = (const float2*)(gq + hc + c);
        const float2* gkp = (const float2*)(gk + hc + c);
#pragma unroll
        for (int j = 0; j < 4; j++) {
            float2 f = __half22float2(hv[j]);
            float2 a = gqp[j], b = gkp[j];
            hv[j] = __floats2half2_rn(f.x * sc * a.x * b.x, f.y * sc * a.y * b.y);
        }
        *(uint4*)&Qs[r * AT_STRIDE + c] = v;
    }
    __syncthreads();

    uint32_t qf[8][4];
#pragma unroll
    for (int kk = 0; kk < 8; kk++) {
        int mr = wid * 16 + (lane & 7) + ((lane >> 3) & 1) * 8;
        int mc = kk * 16 + (lane >> 4) * 8;
        ldmx4(qf[kk][0], qf[kk][1], qf[kk][2], qf[kk][3], &Qs[mr * AT_STRIDE + mc]);
    }

    float oacc[16][4];
#pragma unroll
    for (int i = 0; i < 16; i++)
#pragma unroll
        for (int j = 0; j < 4; j++) oacc[i][j] = 0.f;
    float s0 = 0.f, s1 = 0.f;

    for (int chk = 0; chk < AT_NCH; chk++) {
        CP_WAIT1();
        __syncthreads();
        if (chk + 2 < AT_NCH) load_kv(chk + 2);
        else CP_COMMIT();

        const __half* Kc = KV + (chk % 3) * AT_STAGE;
        const __half* Vc = Kc + AT_KV_CHUNK;

        float sacc[4][4];
#pragma unroll
        for (int t = 0; t < 4; t++)
#pragma unroll
            for (int j = 0; j < 4; j++) sacc[t][j] = 0.f;
#pragma unroll
        for (int kk = 0; kk < 8; kk++) {
#pragma unroll
            for (int half = 0; half < 2; half++) {
                uint32_t b0[2], b1[2];
                int nr = half * 16 + (lane & 7) + ((lane >> 4) ? 8 : 0);
                int nc = kk * 16 + (((lane >> 3) & 1) ? 8 : 0);
                ldmx4(b0[0], b0[1], b1[0], b1[1], &Kc[nr * AT_STRIDE + nc]);
                mma16816(sacc[half * 2 + 0], qf[kk], b0);
                mma16816(sacc[half * 2 + 1], qf[kk], b1);
            }
        }

        uint32_t pf[2][4];
        if (chk < 8) {
#pragma unroll
            for (int nt = 0; nt < 4; nt++) {
                int c0 = chk * 32 + nt * 8 + 2 * (lane & 3);
                float k0 = kscale[c0], k1 = kscale[c0 + 1];
                float e0 = __expf(sacc[nt][0] * k0);
                float e1 = __expf(sacc[nt][1] * k1);
                float e2 = __expf(sacc[nt][2] * k0);
                float e3 = __expf(sacc[nt][3] * k1);
                s0 += e0 + e1;
                s1 += e2 + e3;
                pf[nt >> 1][(nt & 1) * 2 + 0] = h2_as_u32(__floats2half2_rn(e0, e1));
                pf[nt >> 1][(nt & 1) * 2 + 1] = h2_as_u32(__floats2half2_rn(e2, e3));
            }
        } else {
#pragma unroll
            for (int nt = 0; nt < 4; nt++) {
                int c0 = chk * 32 + nt * 8 + 2 * (lane & 3);
                float k0 = kscale[c0], k1 = kscale[c0 + 1];
                float e0 = (c0 < KVLEN) ? __expf(sacc[nt][0] * k0) : 0.f;
                float e1 = (c0 + 1 < KVLEN) ? __expf(sacc[nt][1] * k1) : 0.f;
                float e2 = (c0 < KVLEN) ? __expf(sacc[nt][2] * k0) : 0.f;
                float e3 = (c0 + 1 < KVLEN) ? __expf(sacc[nt][3] * k1) : 0.f;
                s0 += e0 + e1;
                s1 += e2 + e3;
                pf[nt >> 1][(nt & 1) * 2 + 0] = h2_as_u32(__floats2half2_rn(e0, e1));
                pf[nt >> 1][(nt & 1) * 2 + 1] = h2_as_u32(__floats2half2_rn(e2, e3));
            }
        }

#pragma unroll
        for (int np = 0; np < 8; np++) {
#pragma unroll
            for (int kh = 0; kh < 2; kh++) {
                uint32_t v0[2], v1[2];
                int vr = kh * 16 + (lane & 7) + ((lane >> 3) & 1) * 8;
                int vc = np * 16 + (lane >> 4) * 8;
                ldmx4t(v0[0], v0[1], v1[0], v1[1], &Vc[vr * AT_STRIDE + vc]);
                mma16816(oacc[2 * np + 0], pf[kh], v0);
                mma16816(oacc[2 * np + 1], pf[kh], v1);
            }
        }
    }

    s0 += __shfl_xor_sync(0xffffffffu, s0, 1);
    s0 += __shfl_xor_sync(0xffffffffu, s0, 2);
    s1 += __shfl_xor_sync(0xffffffffu, s1, 1);
    s1 += __shfl_xor_sync(0xffffffffu, s1, 2);
    float inv0 = 1.0f / s0, inv1 = 1.0f / s1;

    int r0 = m0 + wid * 16 + (lane >> 2);
    size_t o0 = (size_t)r0 * DIM + hc;
    size_t o1 = (size_t)(r0 + 8) * DIM + hc;
#pragma unroll
    for (int nt = 0; nt < 16; nt++) {
        int c = nt * 8 + 2 * (lane & 3);
        *(float2*)&out[o0 + c] = make_float2(oacc[nt][0] * inv0, oacc[nt][1] * inv0);
        *(float2*)&out[o1 + c] = make_float2(oacc[nt][2] * inv1, oacc[nt][3] * inv1);
    }
}

// ---------------- launcher ----------------
extern "C" void kernel_launch(void* const* d_in, const int* in_sizes, int n_in,
                              void* d_out, int out_size) {
    const float* hidden = (const float*)d_in[0];
    const float* enc = (const float*)d_in[1];
    const float* wq = (const float*)d_in[2];
    const float* bq = (const float*)d_in[3];
    const float* wk = (const float*)d_in[4];
    const float* bk = (const float*)d_in[5];
    const float* wv = (const float*)d_in[6];
    const float* bv = (const float*)d_in[7];
    const float* gq = (const float*)d_in[8];
    const float* gk = (const float*)d_in[9];
    float* out = (float*)d_out;

    void* p;
    cudaGetSymbolAddress(&p, g_Hh);    __half* Hh = (__half*)p;
    cudaGetSymbolAddress(&p, g_Eh);    __half* Eh = (__half*)p;
    cudaGetSymbolAddress(&p, g_Wqh);   __half* Wqh = (__half*)p;
    cudaGetSymbolAddress(&p, g_Wkh);   __half* Wkh = (__half*)p;
    cudaGetSymbolAddress(&p, g_Wvh);   __half* Wvh = (__half*)p;
    cudaGetSymbolAddress(&p, g_Qh);    __half* Qh = (__half*)p;
    cudaGetSymbolAddress(&p, g_Kh);    __half* Kh = (__half*)p;
    cudaGetSymbolAddress(&p, g_Vh);    __half* Vh = (__half*)p;
    cudaGetSymbolAddress(&p, g_ssq_q); float* ssq_q = (float*)p;
    cudaGetSymbolAddress(&p, g_ssq_k); float* ssq_k = (float*)p;

    // launch 0: all conversions + ssq zeroing
    k_prep<<<6144, 256>>>(hidden, wq, wk, wv, enc);
    // launch 1: ALL projections (KV CTAs first, hidden inside the Q-GEMM waves)
    cudaFuncSetAttribute(k_proj_all, cudaFuncAttributeMaxDynamicSharedMemorySize, P_SMEM);
    k_proj_all<<<KV_CTAS + 40 * 128, 128, P_SMEM>>>(Hh, Eh, Wqh, Wkh, Wvh,
                                                    bq, bk, bv, Qh, Kh, Vh,
                                                    ssq_q, ssq_k);
    // launch 2: streaming flash attention
    cudaFuncSetAttribute(k_attn, cudaFuncAttributeMaxDynamicSharedMemorySize, AT_SMEM);
    k_attn<<<dim3(SQ / 64, NHEADS), 128, AT_SMEM>>>(gq, gk, out);
}

// round 16
// speedup vs baseline: 1.0567x; 1.0157x over previous
#include <cuda_runtime.h>
#include <cuda_fp16.h>
#include <stdint.h>

#define DIM    5120
#define SQ     16384
#define KVLEN  257
#define KVP    288
#define NHEADS 40
#define HDIM   128
#define INV_DIM (1.0f / 5120.0f)
#define RMS_EPS 1e-6f

// ---------------- scratch (device globals; no allocs allowed) ----------------
__device__ __half g_Hh  [(size_t)SQ * DIM];
__device__ __half g_Eh  [(size_t)KVLEN * DIM];
__device__ __half g_Wqh [(size_t)DIM * DIM];
__device__ __half g_Wkh [(size_t)DIM * DIM];
__device__ __half g_Wvh [(size_t)DIM * DIM];
__device__ __half g_Qh  [(size_t)SQ * DIM];    // raw q (pre-norm), fp16
__device__ __half g_Kh  [(size_t)KVP * DIM];   // raw k; rows >= 257 stay zero
__device__ __half g_Vh  [(size_t)KVP * DIM];   // v; rows >= 257 stay zero
__device__ float  g_ssq_q[SQ];
__device__ float  g_ssq_k[KVLEN];

// ---------------- helpers ----------------
__device__ __forceinline__ uint32_t smem_u32(const void* p) {
    return (uint32_t)__cvta_generic_to_shared(p);
}

__device__ __forceinline__ uint32_t h2_as_u32(__half2 h) {
    return *reinterpret_cast<uint32_t*>(&h);
}

__device__ __forceinline__ void ldmx4(uint32_t& r0, uint32_t& r1, uint32_t& r2, uint32_t& r3,
                                      const __half* p) {
    asm volatile("ldmatrix.sync.aligned.m8n8.x4.shared.b16 {%0,%1,%2,%3}, [%4];"
                 : "=r"(r0), "=r"(r1), "=r"(r2), "=r"(r3)
                 : "r"(smem_u32(p)));
}

__device__ __forceinline__ void ldmx4t(uint32_t& r0, uint32_t& r1, uint32_t& r2, uint32_t& r3,
                                       const __half* p) {
    asm volatile("ldmatrix.sync.aligned.m8n8.x4.trans.shared.b16 {%0,%1,%2,%3}, [%4];"
                 : "=r"(r0), "=r"(r1), "=r"(r2), "=r"(r3)
                 : "r"(smem_u32(p)));
}

__device__ __forceinline__ void mma16816(float* c, const uint32_t* a, const uint32_t* b) {
    asm volatile(
        "mma.sync.aligned.m16n8k16.row.col.f32.f16.f16.f32 "
        "{%0,%1,%2,%3},{%4,%5,%6,%7},{%8,%9},{%0,%1,%2,%3};"
        : "+f"(c[0]), "+f"(c[1]), "+f"(c[2]), "+f"(c[3])
        : "r"(a[0]), "r"(a[1]), "r"(a[2]), "r"(a[3]), "r"(b[0]), "r"(b[1]));
}

__device__ __forceinline__ void cp16(uint32_t dst, const void* src, bool pred) {
    asm volatile("cp.async.cg.shared.global [%0], [%1], 16, %2;"
                 :: "r"(dst), "l"(src), "r"(pred ? 16 : 0) : "memory");
}
#define CP_COMMIT() asm volatile("cp.async.commit_group;" ::: "memory")
#define CP_WAIT1()  asm volatile("cp.async.wait_group 1;" ::: "memory")

// ---------------- merged prep: float4-wide conversions + ssq zeroing ----------------
__device__ __forceinline__ uint2 cvt4(float4 v) {
    uint2 r;
    r.x = h2_as_u32(__floats2half2_rn(v.x, v.y));
    r.y = h2_as_u32(__floats2half2_rn(v.z, v.w));
    return r;
}

__global__ void k_prep(const float* __restrict__ H, const float* __restrict__ Wq,
                       const float* __restrict__ Wk, const float* __restrict__ Wv,
                       const float* __restrict__ E) {
    const size_t PH = (size_t)SQ * DIM / 4;     // float4 counts
    const size_t PW = (size_t)DIM * DIM / 4;
    const size_t PE = (size_t)KVLEN * DIM / 4;
    size_t i0 = (size_t)blockIdx.x * blockDim.x + threadIdx.x;
    size_t st = (size_t)gridDim.x * blockDim.x;
    if (i0 < SQ) g_ssq_q[i0] = 0.f;
    if (i0 < KVLEN) g_ssq_k[i0] = 0.f;
    const size_t total = PH + 3 * PW + PE;
    for (size_t i = i0; i < total; i += st) {
        if (i < PH) {
            ((uint2*)g_Hh)[i] = cvt4(((const float4*)H)[i]);
        } else if (i < PH + PW) {
            size_t j = i - PH;
            ((uint2*)g_Wqh)[j] = cvt4(((const float4*)Wq)[j]);
        } else if (i < PH + 2 * PW) {
            size_t j = i - PH - PW;
            ((uint2*)g_Wkh)[j] = cvt4(((const float4*)Wk)[j]);
        } else if (i < PH + 3 * PW) {
            size_t j = i - PH - 2 * PW;
            ((uint2*)g_Wvh)[j] = cvt4(((const float4*)Wv)[j]);
        } else {
            size_t j = i - PH - 3 * PW;
            ((uint2*)g_Eh)[j] = cvt4(((const float4*)E)[j]);
        }
    }
}

// ---------------- projection GEMM core (r12 proven: 4 warps, 64x64, BK=32, 3-stage) ----
#define P_STAGE  10240
#define P_SMEM   (3 * P_STAGE * 2)
#define P_NIT    (DIM / 32)

__device__ __forceinline__
void proj_body(const __half* __restrict__ A, const __half* __restrict__ W,
               const float* __restrict__ bias, int M,
               __half* __restrict__ out, float* __restrict__ ssq,
               int m0, int n0, __half* smh) {
    const int tid = threadIdx.x, lane = tid & 31, wid = tid >> 5;
    const int wm = wid & 1, wn = wid >> 1;

    auto load_stage = [&](int s) {
        const int kk = s * 32;
        __half* st = smh + (s % 3) * P_STAGE;
#pragma unroll
        for (int j = 0; j < 4; j++) {
            int ch = tid + j * 128;
            int r = ch >> 2, c16 = ch & 3;
            int row = m0 + r;
            bool ok = row < M;
            cp16(smem_u32(&st[r * 40 + c16 * 8]),
                 A + (size_t)(ok ? row : 0) * DIM + kk + c16 * 8, ok);
        }
        __half* bt = st + 5120;
#pragma unroll
        for (int j = 0; j < 4; j++) {
            int ch = tid + j * 128;
            int r = ch >> 2, c16 = ch & 3;
            cp16(smem_u32(&bt[r * 40 + c16 * 8]),
                 W + (size_t)(n0 + r) * DIM + kk + c16 * 8, true);
        }
        CP_COMMIT();
    };

    float acc[4][8][4];
#pragma unroll
    for (int i = 0; i < 4; i++)
#pragma unroll
        for (int j = 0; j < 8; j++)
#pragma unroll
            for (int k = 0; k < 4; k++) acc[i][j][k] = 0.f;

    load_stage(0);
    load_stage(1);

    for (int i = 0; i < P_NIT; i++) {
        CP_WAIT1();
        __syncthreads();
        if (i + 2 < P_NIT) load_stage(i + 2);
        else CP_COMMIT();

        const __half* a_s = smh + (i % 3) * P_STAGE;
        const __half* b_s = a_s + 5120;

#pragma unroll
        for (int ks = 0; ks < 32; ks += 16) {
            uint32_t af[4][4];
#pragma unroll
            for (int mf = 0; mf < 4; mf++) {
                int mr = wm * 64 + mf * 16 + (lane & 7) + ((lane >> 3) & 1) * 8;
                int mc = ks + (lane >> 4) * 8;
                ldmx4(af[mf][0], af[mf][1], af[mf][2], af[mf][3], &a_s[mr * 40 + mc]);
            }
#pragma unroll
            for (int np = 0; np < 4; np++) {
                uint32_t b0[2], b1[2];
                int nr = wn * 64 + np * 16 + (lane & 7) + ((lane >> 4) ? 8 : 0);
                int nc = ks + (((lane >> 3) & 1) ? 8 : 0);
                ldmx4(b0[0], b0[1], b1[0], b1[1], &b_s[nr * 40 + nc]);
#pragma unroll
                for (int mf = 0; mf < 4; mf++) {
                    mma16816(acc[mf][2 * np + 0], af[mf], b0);
                    mma16816(acc[mf][2 * np + 1], af[mf], b1);
                }
            }
        }
    }

#pragma unroll
    for (int mf = 0; mf < 4; mf++) {
#pragma unroll
        for (int rh = 0; rh < 2; rh++) {
            int gr = m0 + wm * 64 + mf * 16 + (lane >> 2) + rh * 8;
            if (gr >= M) continue;
            float s = 0.f;
#pragma unroll
            for (int nf = 0; nf < 8; nf++) {
                int gc = n0 + wn * 64 + nf * 8 + 2 * (lane & 3);
                float v0 = acc[mf][nf][rh * 2 + 0] + bias[gc];
                float v1 = acc[mf][nf][rh * 2 + 1] + bias[gc + 1];
                s += v0 * v0 + v1 * v1;
                *(__half2*)&out[(size_t)gr * DIM + gc] = __floats2half2_rn(v0, v1);
            }
            if (ssq) atomicAdd(&ssq[gr], s);
        }
    }
}

// ---- ALL projections in one launch: bids 0..239 = K/V tiles, 240.. = Q tiles ----
#define KV_CTAS 240   // 40 n-tiles x 3 m-tiles x 2 (K,V)

__global__ __launch_bounds__(128, 3)
void k_proj_all(const __half* __restrict__ Hh, const __half* __restrict__ Eh,
                const __half* __restrict__ Wq, const __half* __restrict__ Wk,
                const __half* __restrict__ Wv,
                const float* __restrict__ bq, const float* __restrict__ bk,
                const float* __restrict__ bv,
                __half* __restrict__ Qh, __half* __restrict__ Kh,
                __half* __restrict__ Vh,
                float* __restrict__ ssq_q, float* __restrict__ ssq_k) {
    extern __shared__ __align__(16) __half smh[];
    int bid = blockIdx.x;
    if (bid < KV_CTAS) {
        int n0 = (bid % 40) * 128;
        int rest = bid / 40;            // 0..5
        int m0 = (rest % 3) * 128;
        if (rest < 3)
            proj_body(Eh, Wk, bk, KVLEN, Kh, ssq_k, m0, n0, smh);
        else
            proj_body(Eh, Wv, bv, KVLEN, Vh, (float*)0, m0, n0, smh);
    } else {
        int q = bid - KV_CTAS;
        int n0 = (q % 40) * 128;
        int m0 = (q / 40) * 128;
        proj_body(Hh, Wq, bq, SQ, Qh, ssq_q, m0, n0, smh);
    }
}

// ---------------- register-streaming flash attention: 32-row KV chunks (r14 proven) ----
#define AT_STRIDE 136
#define AT_QS_HALFS (64 * AT_STRIDE)
#define AT_KV_CHUNK (32 * AT_STRIDE)
#define AT_STAGE    (2 * AT_KV_CHUNK)
#define AT_SMEM     ((AT_QS_HALFS + 3 * AT_STAGE) * 2 + KVP * 4)
#define AT_NCH      9

__global__ __launch_bounds__(128, 3)
void k_attn(const float* __restrict__ gq, const float* __restrict__ gk,
            float* __restrict__ out) {
    extern __shared__ __align__(16) char smem[];
    __half* Qs = (__half*)smem;
    __half* KV = (__half*)(smem + AT_QS_HALFS * 2);
    float* kscale = (float*)(smem + (AT_QS_HALFS + 3 * AT_STAGE) * 2);

    const int tid = threadIdx.x, lane = tid & 31, wid = tid >> 5;
    const int m0 = blockIdx.x * 64;
    const size_t hc = (size_t)blockIdx.y * HDIM;
    const float SCALE = 0.088388347648318447f;

    for (int c = tid; c < KVP; c += 128)
        kscale[c] = (c < KVLEN) ? SCALE * rsqrtf(g_ssq_k[c] * INV_DIM + RMS_EPS) : 0.f;

    auto load_kv = [&](int s) {
        __half* base = KV + (s % 3) * AT_STAGE;
        const __half* Ksrc = g_Kh + (size_t)(s * 32) * DIM + hc;
        const __half* Vsrc = g_Vh + (size_t)(s * 32) * DIM + hc;
#pragma unroll
        for (int j = 0; j < 4; j++) {
            int ch = tid + j * 128;
            int r = ch >> 4, c8 = (ch & 15) * 8;
            cp16(smem_u32(&base[r * AT_STRIDE + c8]), Ksrc + (size_t)r * DIM + c8, true);
        }
#pragma unroll
        for (int j = 0; j < 4; j++) {
            int ch = tid + j * 128;
            int r = ch >> 4, c8 = (ch & 15) * 8;
            cp16(smem_u32(&base[AT_KV_CHUNK + r * AT_STRIDE + c8]),
                 Vsrc + (size_t)r * DIM + c8, true);
        }
        CP_COMMIT();
    };
    load_kv(0);
    load_kv(1);

#pragma unroll
    for (int i = 0; i < 8; i++) {
        int idx = tid + 128 * i;
        int r = idx >> 4, c = (idx & 15) * 8;
        float sc = rsqrtf(g_ssq_q[m0 + r] * INV_DIM + RMS_EPS);
        uint4 v = *(const uint4*)&g_Qh[(size_t)(m0 + r) * DIM + hc + c];
        __half2* hv = (__half2*)&v;
        const float2* gqp = (const float2*)(gq + hc + c);
        const float2* gkp = (const float2*)(gk + hc + c);
#pragma unroll
        for (int j = 0; j < 4; j++) {
            float2 f = __half22float2(hv[j]);
            float2 a = gqp[j], b = gkp[j];
            hv[j] = __floats2half2_rn(f.x * sc * a.x * b.x, f.y * sc * a.y * b.y);
        }
        *(uint4*)&Qs[r * AT_STRIDE + c] = v;
    }
    __syncthreads();

    uint32_t qf[8][4];
#pragma unroll
    for (int kk = 0; kk < 8; kk++) {
        int mr = wid * 16 + (lane & 7) + ((lane >> 3) & 1) * 8;
        int mc = kk * 16 + (lane >> 4) * 8;
        ldmx4(qf[kk][0], qf[kk][1], qf[kk][2], qf[kk][3], &Qs[mr * AT_STRIDE + mc]);
    }

    float oacc[16][4];
#pragma unroll
    for (int i = 0; i < 16; i++)
#pragma unroll
        for (int j = 0; j < 4; j++) oacc[i][j] = 0.f;
    float s0 = 0.f, s1 = 0.f;

    for (int chk = 0; chk < AT_NCH; chk++) {
        CP_WAIT1();
        __syncthreads();
        if (chk + 2 < AT_NCH) load_kv(chk + 2);
        else CP_COMMIT();

        const __half* Kc = KV + (chk % 3) * AT_STAGE;
        const __half* Vc = Kc + AT_KV_CHUNK;

        float sacc[4][4];
#pragma unroll
        for (int t = 0; t < 4; t++)
#pragma unroll
            for (int j = 0; j < 4; j++) sacc[t][j] = 0.f;
#pragma unroll
        for (int kk = 0; kk < 8; kk++) {
#pragma unroll
            for (int half = 0; half < 2; half++) {
                uint32_t b0[2], b1[2];
                int nr = half * 16 + (lane & 7) + ((lane >> 4) ? 8 : 0);
                int nc = kk * 16 + (((lane >> 3) & 1) ? 8 : 0);
                ldmx4(b0[0], b0[1], b1[0], b1[1], &Kc[nr * AT_STRIDE + nc]);
                mma16816(sacc[half * 2 + 0], qf[kk], b0);
                mma16816(sacc[half * 2 + 1], qf[kk], b1);
            }
        }

        uint32_t pf[2][4];
        if (chk < 8) {
#pragma unroll
            for (int nt = 0; nt < 4; nt++) {
                int c0 = chk * 32 + nt * 8 + 2 * (lane & 3);
                float k0 = kscale[c0], k1 = kscale[c0 + 1];
                float e0 = __expf(sacc[nt][0] * k0);
                float e1 = __expf(sacc[nt][1] * k1);
                float e2 = __expf(sacc[nt][2] * k0);
                float e3 = __expf(sacc[nt][3] * k1);
                s0 += e0 + e1;
                s1 += e2 + e3;
                pf[nt >> 1][(nt & 1) * 2 + 0] = h2_as_u32(__floats2half2_rn(e0, e1));
                pf[nt >> 1][(nt & 1) * 2 + 1] = h2_as_u32(__floats2half2_rn(e2, e3));
            }
        } else {
#pragma unroll
            for (int nt = 0; nt < 4; nt++) {
                int c0 = chk * 32 + nt * 8 + 2 * (lane & 3);
                float k0 = kscale[c0], k1 = kscale[c0 + 1];
                float e0 = (c0 < KVLEN) ? __expf(sacc[nt][0] * k0) : 0.f;
                float e1 = (c0 + 1 < KVLEN) ? __expf(sacc[nt][1] * k1) : 0.f;
                float e2 = (c0 < KVLEN) ? __expf(sacc[nt][2] * k0) : 0.f;
                float e3 = (c0 + 1 < KVLEN) ? __expf(sacc[nt][3] * k1) : 0.f;
                s0 += e0 + e1;
                s1 += e2 + e3;
                pf[nt >> 1][(nt & 1) * 2 + 0] = h2_as_u32(__floats2half2_rn(e0, e1));
                pf[nt >> 1][(nt & 1) * 2 + 1] = h2_as_u32(__floats2half2_rn(e2, e3));
            }
        }

#pragma unroll
        for (int np = 0; np < 8; np++) {
#pragma unroll
            for (int kh = 0; kh < 2; kh++) {
                uint32_t v0[2], v1[2];
                int vr = kh * 16 + (lane & 7) + ((lane >> 3) & 1) * 8;
                int vc = np * 16 + (lane >> 4) * 8;
                ldmx4t(v0[0], v0[1], v1[0], v1[1], &Vc[vr * AT_STRIDE + vc]);
                mma16816(oacc[2 * np + 0], pf[kh], v0);
                mma16816(oacc[2 * np + 1], pf[kh], v1);
            }
        }
    }

    s0 += __shfl_xor_sync(0xffffffffu, s0, 1);
    s0 += __shfl_xor_sync(0xffffffffu, s0, 2);
    s1 += __shfl_xor_sync(0xffffffffu, s1, 1);
    s1 += __shfl_xor_sync(0xffffffffu, s1, 2);
    float inv0 = 1.0f / s0, inv1 = 1.0f / s1;

    int r0 = m0 + wid * 16 + (lane >> 2);
    size_t o0 = (size_t)r0 * DIM + hc;
    size_t o1 = (size_t)(r0 + 8) * DIM + hc;
#pragma unroll
    for (int nt = 0; nt < 16; nt++) {
        int c = nt * 8 + 2 * (lane & 3);
        *(float2*)&out[o0 + c] = make_float2(oacc[nt][0] * inv0, oacc[nt][1] * inv0);
        *(float2*)&out[o1 + c] = make_float2(oacc[nt][2] * inv1, oacc[nt][3] * inv1);
    }
}

// ---------------- launcher ----------------
extern "C" void kernel_launch(void* const* d_in, const int* in_sizes, int n_in,
                              void* d_out, int out_size) {
    const float* hidden = (const float*)d_in[0];
    const float* enc = (const float*)d_in[1];
    const float* wq = (const float*)d_in[2];
    const float* bq = (const float*)d_in[3];
    const float* wk = (const float*)d_in[4];
    const float* bk = (const float*)d_in[5];
    const float* wv = (const float*)d_in[6];
    const float* bv = (const float*)d_in[7];
    const float* gq = (const float*)d_in[8];
    const float* gk = (const float*)d_in[9];
    float* out = (float*)d_out;

    void* p;
    cudaGetSymbolAddress(&p, g_Hh);    __half* Hh = (__half*)p;
    cudaGetSymbolAddress(&p, g_Eh);    __half* Eh = (__half*)p;
    cudaGetSymbolAddress(&p, g_Wqh);   __half* Wqh = (__half*)p;
    cudaGetSymbolAddress(&p, g_Wkh);   __half* Wkh = (__half*)p;
    cudaGetSymbolAddress(&p, g_Wvh);   __half* Wvh = (__half*)p;
    cudaGetSymbolAddress(&p, g_Qh);    __half* Qh = (__half*)p;
    cudaGetSymbolAddress(&p, g_Kh);    __half* Kh = (__half*)p;
    cudaGetSymbolAddress(&p, g_Vh);    __half* Vh = (__half*)p;
    cudaGetSymbolAddress(&p, g_ssq_q); float* ssq_q = (float*)p;
    cudaGetSymbolAddress(&p, g_ssq_k); float* ssq_k = (float*)p;

    // launch 0: all conversions (float4-wide) + ssq zeroing
    k_prep<<<6144, 256>>>(hidden, wq, wk, wv, enc);
    // launch 1: ALL projections (KV CTAs first, hidden inside the Q-GEMM waves)
    cudaFuncSetAttribute(k_proj_all, cudaFuncAttributeMaxDynamicSharedMemorySize, P_SMEM);
    k_proj_all<<<KV_CTAS + 40 * 128, 128, P_SMEM>>>(Hh, Eh, Wqh, Wkh, Wvh,
                                                    bq, bk, bv, Qh, Kh, Vh,
                                                    ssq_q, ssq_k);
    // launch 2: streaming flash attention
    cudaFuncSetAttribute(k_attn, cudaFuncAttributeMaxDynamicSharedMemorySize, AT_SMEM);
    k_attn<<<dim3(SQ / 64, NHEADS), 128, AT_SMEM>>>(gq, gk, out);
}